// round 4
// baseline (speedup 1.0000x reference)
#include <cuda_runtime.h>
#include <math_constants.h>

// Problem constants
#define N_BATCH 4
#define C_CH    128
#define S_FR    31
#define HW      704           // 32*22
#define NS      120           // 4*(31-1)
#define NPIX    87296         // 4*31*704 (= 64*1364)
#define TOPK    16
#define NB      128           // denominator bins (power of 2)
#define LOG2E   1.4426950408889634f
#define LN2F    0.6931471805599453f

// Scratch (device globals — no allocation allowed)
__device__ float  g_X0[NS * HW];        // a values
__device__ float  g_BL[NS * HW];        // b * log2e (order-preserving)
__device__ float  g_TB[NS * 32];        // [0..15] top desc, [16..31] bottom asc
__device__ float4 g_BINS[NS * NB];      // per row: (S0, S1, S2/2, S3/6) per bin
__device__ float2 g_ROW[NS];            // per row: (lo, W)

__device__ __forceinline__ float ex2(float x) {
    float r;
    asm("ex2.approx.f32 %0, %1;" : "=f"(r) : "f"(x));
    return r;
}

// ---------------------------------------------------------------------------
// Kernel A: channel contraction, 4 threads per pixel (split-C) for deep MLP.
// Block: 256 threads = 64 pixels x 4 channel quarters.
// ---------------------------------------------------------------------------
__global__ void __launch_bounds__(256, 8)
kA(const float* __restrict__ x,
   const float* __restrict__ w1, const float* __restrict__ b1,
   const float* __restrict__ w2, const float* __restrict__ b2) {
    __shared__ float sw1[C_CH], sw2[C_CH];
    __shared__ float p1[4][64], p2[4][64];
    int tid = threadIdx.x;          // 0..255
    if (tid < C_CH) { sw1[tid] = w1[tid]; sw2[tid] = w2[tid]; }
    __syncthreads();

    int quarter = tid >> 6;         // 0..3
    int px      = tid & 63;
    int p = blockIdx.x * 64 + px;   // NPIX = 64*1364 exactly
    int n = p / (S_FR * HW);
    int q = p - n * (S_FR * HW);

    const float* xp = x + (size_t)n * (C_CH * S_FR * HW)
                        + (size_t)(quarter * 32) * (S_FR * HW) + q;
    const float* pw1 = sw1 + quarter * 32;
    const float* pw2 = sw2 + quarter * 32;

    float y1 = 0.f, y2 = 0.f;
#pragma unroll
    for (int cb = 0; cb < 32; cb += 16) {
        float v[16];
#pragma unroll
        for (int u = 0; u < 16; u++) v[u] = xp[(cb + u) * (S_FR * HW)];
#pragma unroll
        for (int u = 0; u < 16; u++) {
            y1 = fmaf(v[u], pw1[cb + u], y1);
            y2 = fmaf(v[u], pw2[cb + u], y2);
        }
    }
    p1[quarter][px] = y1;
    p2[quarter][px] = y2;
    __syncthreads();

    if (quarter == 0) {
        y1 = (p1[0][px] + p1[1][px]) + (p1[2][px] + p1[3][px]);
        y2 = (p2[0][px] + p2[1][px]) + (p2[2][px] + p2[3][px]);
        int f = q / HW;
        int i = q - f * HW;
        if (f < S_FR - 1) g_X0[(n * (S_FR - 1) + f) * HW + i] = y1 + b1[0];
        if (f >= 1)       g_BL[(n * (S_FR - 1) + f - 1) * HW + i] = (y2 + b2[0]) * LOG2E;
    }
}

// ---------------------------------------------------------------------------
// Kernel B: per-row min/max + moment bins + top/bottom-16 selection.
// 256 threads/block, 120 blocks. No sort: warp0 iterative top-16 on sv,
// warp1 iterative bottom-16 on sv2 (separate copies; consumption-safe).
// ---------------------------------------------------------------------------
__global__ void kB() {
    __shared__ float sv[HW], sv2[HW];
    __shared__ float binS0[NB], binS1[NB], binS2[NB], binS3[NB];
    __shared__ float rmin[8], rmax[8];
    __shared__ float s_lo, s_W, s_invW;
    int r = blockIdx.x;
    int tid = threadIdx.x;   // 256
    int lane = tid & 31, wid = tid >> 5;

    float lmin = CUDART_INF_F, lmax = -CUDART_INF_F;
    for (int j = tid; j < HW; j += 256) {
        float v = g_BL[r * HW + j];
        sv[j] = v; sv2[j] = v;
        lmin = fminf(lmin, v);
        lmax = fmaxf(lmax, v);
    }
    if (tid < NB) { binS0[tid] = 0.f; binS1[tid] = 0.f; binS2[tid] = 0.f; binS3[tid] = 0.f; }
#pragma unroll
    for (int o = 16; o; o >>= 1) {
        lmin = fminf(lmin, __shfl_xor_sync(0xffffffffu, lmin, o));
        lmax = fmaxf(lmax, __shfl_xor_sync(0xffffffffu, lmax, o));
    }
    if (lane == 0) { rmin[wid] = lmin; rmax[wid] = lmax; }
    __syncthreads();
    if (tid == 0) {
        float lo = rmin[0], hi = rmax[0];
#pragma unroll
        for (int w = 1; w < 8; w++) { lo = fminf(lo, rmin[w]); hi = fmaxf(hi, rmax[w]); }
        float W = (hi - lo) * (1.0f / NB) + 1e-30f;
        s_lo = lo; s_W = W; s_invW = 1.0f / W;
        g_ROW[r] = make_float2(lo, W);
    }
    __syncthreads();

    {
        float lo = s_lo, W = s_W, invW = s_invW;
        for (int j = tid; j < HW; j += 256) {
            float v = sv[j];
            int m = (int)((v - lo) * invW);
            m = (m > NB - 1) ? NB - 1 : (m < 0 ? 0 : m);
            float d = v - fmaf((float)m + 0.5f, W, lo);
            atomicAdd(&binS0[m], 1.0f);
            atomicAdd(&binS1[m], d);
            atomicAdd(&binS2[m], 0.5f * d * d);
            atomicAdd(&binS3[m], (1.0f / 6.0f) * d * d * d);
        }
    }
    __syncthreads();
    if (tid < NB)
        g_BINS[r * NB + tid] = make_float4(binS0[tid], binS1[tid], binS2[tid], binS3[tid]);

    if (wid == 0) {
        // top-16 descending, consumption on sv
        for (int it = 0; it < TOPK; it++) {
            float lm = -CUDART_INF_F; int li = 0;
            for (int j = lane; j < HW; j += 32) {
                float v = sv[j];
                if (v > lm) { lm = v; li = j; }
            }
#pragma unroll
            for (int o = 16; o; o >>= 1) {
                float ov = __shfl_xor_sync(0xffffffffu, lm, o);
                int   oi = __shfl_xor_sync(0xffffffffu, li, o);
                if (ov > lm || (ov == lm && oi < li)) { lm = ov; li = oi; }
            }
            if (lane == 0) { g_TB[r * 32 + it] = lm; sv[li] = -CUDART_INF_F; }
            __syncwarp();
        }
    } else if (wid == 1) {
        // bottom-16 ascending, consumption on sv2
        for (int it = 0; it < TOPK; it++) {
            float lm = CUDART_INF_F; int li = 0;
            for (int j = lane; j < HW; j += 32) {
                float v = sv2[j];
                if (v < lm) { lm = v; li = j; }
            }
#pragma unroll
            for (int o = 16; o; o >>= 1) {
                float ov = __shfl_xor_sync(0xffffffffu, lm, o);
                int   oi = __shfl_xor_sync(0xffffffffu, li, o);
                if (ov < lm || (ov == lm && oi < li)) { lm = ov; li = oi; }
            }
            if (lane == 0) { g_TB[r * 32 + 16 + it] = lm; sv2[li] = CUDART_INF_F; }
            __syncwarp();
        }
    }
}

// ---------------------------------------------------------------------------
// Kernel C: denominator via geometric-chain over bins (FMA pipe),
// then exact top-k numerators. 11 chunks of 64 pixels per row.
// ---------------------------------------------------------------------------
__global__ void kC(float* __restrict__ out) {
    __shared__ float4 sb[NB];
    __shared__ float ssel[32];
    int r = blockIdx.x / 11;
    int chunk = blockIdx.x - r * 11;
    int tid = threadIdx.x;   // 64

    sb[tid]      = g_BINS[r * NB + tid];
    sb[tid + 64] = g_BINS[r * NB + 64 + tid];
    if (tid < 32) ssel[tid] = g_TB[r * 32 + tid];
    __syncthreads();

    int i = chunk * 64 + tid;
    float a = g_X0[r * HW + i];
    float2 rp = g_ROW[r];
    float lo = rp.x, W = rp.y;

    bool pos = (a >= 0.f);
    float msc = pos ? a * ssel[0] : a * ssel[16];
    float nm = -msc;
    int mask = pos ? (NB - 1) : 0;
    float cs = pos ? fmaf((float)NB - 0.5f, W, lo) : fmaf(0.5f, W, lo);

    float rho = ex2(-fabsf(a) * W);                 // <= 1, decaying chain
    float rho4 = rho * rho; rho4 *= rho4;
    float p0 = ex2(fmaf(a, cs, nm));
    float p1 = p0 * rho, p2 = p1 * rho, p3 = p2 * rho;
    float L = a * LN2F;

    float D0 = 0.f, D1 = 0.f, D2 = 0.f, D3 = 0.f;
#pragma unroll 4
    for (int m = 0; m < NB; m += 4) {
        float4 c0 = sb[(m + 0) ^ mask];
        float4 c1 = sb[(m + 1) ^ mask];
        float4 c2 = sb[(m + 2) ^ mask];
        float4 c3 = sb[(m + 3) ^ mask];
        D0 = fmaf(p0, fmaf(L, fmaf(L, fmaf(L, c0.w, c0.z), c0.y), c0.x), D0);
        D1 = fmaf(p1, fmaf(L, fmaf(L, fmaf(L, c1.w, c1.z), c1.y), c1.x), D1);
        D2 = fmaf(p2, fmaf(L, fmaf(L, fmaf(L, c2.w, c2.z), c2.y), c2.x), D2);
        D3 = fmaf(p3, fmaf(L, fmaf(L, fmaf(L, c3.w, c3.z), c3.y), c3.x), D3);
        p0 *= rho4; p1 *= rho4; p2 *= rho4; p3 *= rho4;
    }
    float rD = __frcp_rn((D0 + D1) + (D2 + D3));

    const float* sel = pos ? ssel : (ssel + 16);
    float v[TOPK];
#pragma unroll
    for (int k = 0; k < TOPK; k++)
        v[k] = ex2(fmaf(a, sel[k], nm)) * rD;

    // output: idx = i*16 + k ; k2 = i/44 (k-independent)
    int n  = r / (S_FR - 1);
    int sp = r - n * (S_FR - 1);
    int k2 = i / 44;
    int im = i - k2 * 44;
    float4* o = reinterpret_cast<float4*>(
        out + ((size_t)((n * TOPK + k2) * (S_FR - 1) + sp)) * HW + im * 16);
    o[0] = make_float4(v[0],  v[1],  v[2],  v[3]);
    o[1] = make_float4(v[4],  v[5],  v[6],  v[7]);
    o[2] = make_float4(v[8],  v[9],  v[10], v[11]);
    o[3] = make_float4(v[12], v[13], v[14], v[15]);
}

// ---------------------------------------------------------------------------
extern "C" void kernel_launch(void* const* d_in, const int* in_sizes, int n_in,
                              void* d_out, int out_size) {
    const float* x  = (const float*)d_in[0];
    const float* w1 = (const float*)d_in[1];
    const float* b1 = (const float*)d_in[2];
    const float* w2 = (const float*)d_in[3];
    const float* b2 = (const float*)d_in[4];
    float* out = (float*)d_out;

    kA<<<NPIX / 64, 256>>>(x, w1, b1, w2, b2);
    kB<<<NS, 256>>>();
    kC<<<NS * 11, 64>>>(out);
}